// round 13
// baseline (speedup 1.0000x reference)
#include <cuda_runtime.h>
#include <cstdint>

#define U        128
#define G4       512
#define SKIPN    16
#define TSTEPS   128
#define BATCH    64
#define FLATN    16384   // SEQ * UNITS

// Scratch (device globals: allocation-free rule)
__device__ float g_xpe[8192 * 512];      // encoder input projections, row = t*64+b
__device__ float g_flat[BATCH * FLATN];  // decoder outputs (dense GEMM B-matrix)

__device__ __forceinline__ float sigm(float x) { return 1.0f / (1.0f + expf(-x)); }

__device__ __forceinline__ uint32_t smem_u32(const void* p) {
    uint32_t a;
    asm("{ .reg .u64 t; cvta.to.shared.u64 t, %1; cvt.u32.u64 %0, t; }" : "=r"(a) : "l"(p));
    return a;
}
__device__ __forceinline__ void cp16(uint32_t dst, const float* src) {
    asm volatile("cp.async.cg.shared.global [%0], [%1], 16;" :: "r"(dst), "l"(src));
}
__device__ __forceinline__ uint32_t f2tf32(float f) {
    uint32_t r;
    asm("cvt.rna.tf32.f32 %0, %1;" : "=r"(r) : "f"(f));
    return r;
}
__device__ __forceinline__ void mma16n8k8(float* c, const uint32_t* a, uint32_t b0, uint32_t b1) {
    asm volatile(
        "mma.sync.aligned.m16n8k8.row.col.f32.tf32.tf32.f32 "
        "{%0,%1,%2,%3}, {%4,%5,%6,%7}, {%8,%9}, {%0,%1,%2,%3};"
        : "+f"(c[0]), "+f"(c[1]), "+f"(c[2]), "+f"(c[3])
        : "r"(a[0]), "r"(a[1]), "r"(a[2]), "r"(a[3]), "r"(b0), "r"(b1));
}
__device__ __forceinline__ uint32_t ctarank() {
    uint32_t r; asm("mov.u32 %0, %%cluster_ctarank;" : "=r"(r)); return r;
}
__device__ __forceinline__ uint32_t mapa_u32(uint32_t a, uint32_t rank) {
    uint32_t o; asm("mapa.shared::cluster.u32 %0, %1, %2;" : "=r"(o) : "r"(a), "r"(rank)); return o;
}
__device__ __forceinline__ void st_cluster_f32(uint32_t addr, float v) {
    asm volatile("st.shared::cluster.f32 [%0], %1;" :: "r"(addr), "f"(v) : "memory");
}
#define CLUSTER_SYNC() do { \
    asm volatile("barrier.cluster.arrive.aligned;" ::: "memory"); \
    asm volatile("barrier.cluster.wait.aligned;" ::: "memory"); \
} while (0)

// ================= Kernel 1: encoder input projection =================
__global__ __launch_bounds__(128) void k_xproj(const float* __restrict__ X,
                                               const float* __restrict__ Wk,
                                               const float* __restrict__ bias) {
    __shared__ float As[128 * 16];   // [k][r] transposed
    const int tid  = threadIdx.x;
    const int row0 = blockIdx.x * 16;

    for (int idx = tid; idx < 16 * 128; idx += 128) {
        int r = idx >> 7, m = idx & 127;
        int row = row0 + r;
        int t = row >> 6, b = row & 63;
        As[m * 16 + r] = X[(size_t)b * 32768 + t * 128 + m];
    }
    __syncthreads();

    const int c0 = tid * 4;
    float4 bs = *(const float4*)(bias + c0);
    float acc[16][4];
#pragma unroll
    for (int r = 0; r < 16; r++) { acc[r][0] = bs.x; acc[r][1] = bs.y; acc[r][2] = bs.z; acc[r][3] = bs.w; }

#pragma unroll 4
    for (int k = 0; k < 128; k++) {
        float4 w = *(const float4*)(Wk + k * 512 + c0);
#pragma unroll
        for (int r = 0; r < 16; r++) {
            float a = As[k * 16 + r];
            acc[r][0] = fmaf(a, w.x, acc[r][0]);
            acc[r][1] = fmaf(a, w.y, acc[r][1]);
            acc[r][2] = fmaf(a, w.z, acc[r][2]);
            acc[r][3] = fmaf(a, w.w, acc[r][3]);
        }
    }
#pragma unroll
    for (int r = 0; r < 16; r++) {
        float4 o; o.x = acc[r][0]; o.y = acc[r][1]; o.z = acc[r][2]; o.w = acc[r][3];
        *(float4*)(g_xpe + (size_t)(row0 + r) * 512 + c0) = o;
    }
}

// ====== Kernel 2: clustered skip-LSTM, 2 batches per cluster, 640 thr/CTA ===
// Cluster of 2 CTAs handles batches {2*cid, 2*cid+1}. CTA rank r owns gate
// columns [r*256, r*256+256) and skip columns [r*64, r*64+64).
// Gate threads: tid = 2*col + b (adjacent lanes share weight column -> LDS dedup).
// Skip threads: tid-512 = 2*scl + b. State replicated per batch in both CTAs.
#define L4_WSTRIDE 132   // 132 mod 32 == 4 -> LDS.128 conflict-free
#define L4_OFF_WS   0
#define L4_OFF_K2   (256 * L4_WSTRIDE)                 // 33792
#define L4_OFF_SG   (L4_OFF_K2 + 64 * L4_WSTRIDE)      // 42240 (2 x 512)
#define L4_OFF_SC   (L4_OFF_SG + 1024)                 // 2 x 128
#define L4_OFF_SH   (L4_OFF_SC + 256)                  // 2 x 128
#define L4_OFF_PH   (L4_OFF_SH + 256)                  // 2 x 16 x 128
#define L4_OFF_SPRE (L4_OFF_PH + 4096)                 // 2 batches x 2 parity x 640
#define L4_OFF_XPD  (L4_OFF_SPRE + 2560)               // 2 x 512
#define L4_SMEMF    (L4_OFF_XPD + 1024)
#define L4_SMEM     (L4_SMEMF * 4)                     // 205824 bytes

__device__ __forceinline__ void l4_fill(int tid, int rank, float* ws, float* k2s,
                                        const float* __restrict__ rk,
                                        const float* __restrict__ k2) {
    for (int idx = tid; idx < 256 * 128; idx += 640) {
        int col = idx & 255, k = idx >> 8;
        ws[col * L4_WSTRIDE + k] = rk[k * 512 + rank * 256 + col];
    }
    for (int idx = tid; idx < 64 * 128; idx += 640) {
        int col = idx & 63, k = idx >> 6;
        k2s[col * L4_WSTRIDE + k] = k2[k * 128 + rank * 64 + col];
    }
}

__global__ __launch_bounds__(640, 1) __cluster_dims__(2, 1, 1)
void k_lstm4(
    const float* __restrict__ enc_rk, const float* __restrict__ enc_k2,
    const float* __restrict__ enc_b2, const float* __restrict__ enc_s0p,
    const float* __restrict__ dec_k,  const float* __restrict__ dec_rk,
    const float* __restrict__ dec_k2, const float* __restrict__ dec_b,
    const float* __restrict__ dec_b2, const float* __restrict__ dec_s0p) {
    extern __shared__ __align__(16) float ls[];
    float* ws   = ls + L4_OFF_WS;
    float* k2s  = ls + L4_OFF_K2;
    float* sg   = ls + L4_OFF_SG;
    float* sc   = ls + L4_OFF_SC;
    float* sh   = ls + L4_OFF_SH;
    float* ph   = ls + L4_OFF_PH;
    float* spre = ls + L4_OFF_SPRE;
    float* xpd  = ls + L4_OFF_XPD;

    const int tid  = threadIdx.x;
    const int rank = (int)ctarank();
    const int b0   = (blockIdx.x >> 1) * 2;        // first batch of this cluster
    const uint32_t sb = smem_u32(ls);
    const uint32_t rspre = mapa_u32(sb + L4_OFF_SPRE * 4, 1 - rank);

    // thread roles
    const int col  = tid >> 1;                     // gate: local column (tid<512)
    const int bb   = tid & 1;                      // batch within cluster
    const int gcol = rank * 256 + col;             // global gate column
    const int q    = gcol >> 7;                    // gate quadrant (warp-uniform)
    const int ssl  = (tid - 512) >> 1;             // skip: local column (tid>=512)
    const int sbb  = (tid - 512) & 1;
    const int gs   = rank * 64 + ssl;              // global skip column

    // ---------------- encoder setup ----------------
    l4_fill(tid, rank, ws, k2s, enc_rk, enc_k2);
    for (int i = tid; i < 1024; i += 640) sg[i] = 0.f;
    for (int i = tid; i < 256;  i += 640) sc[i] = 0.f;
    for (int i = tid; i < 4096; i += 640) ph[i] = 0.f;
    float b2 = (tid >= 512) ? enc_b2[gs] : 0.f;
    const float s0e = *enc_s0p;
    const float s0d = *dec_s0p;
    __syncthreads();

    // ---------------- encoder loop ----------------
    for (int t = 0; t < TSTEPS; t++) {
        const int par = (t & 1) * 640;
        if (tid < 512) {
            float a0 = g_xpe[((size_t)t * 64 + b0 + bb) * 512 + gcol];
            float a1 = 0.f, a2 = 0.f, a3 = 0.f;
            const float* sv = sg + bb * 512 + (q << 7);
            const float* w  = ws + col * L4_WSTRIDE;
#pragma unroll 8
            for (int k = 0; k < 128; k += 4) {
                float4 s4 = *(const float4*)(sv + k);
                float4 w4 = *(const float4*)(w + k);
                a0 = fmaf(s4.x, w4.x, a0);
                a1 = fmaf(s4.y, w4.y, a1);
                a2 = fmaf(s4.z, w4.z, a2);
                a3 = fmaf(s4.w, w4.w, a3);
            }
            float acc = (a0 + a1) + (a2 + a3);
            const int si = bb * 1280 + par + gcol;
            spre[si] = acc;
            st_cluster_f32(rspre + si * 4, acc);
        } else {
            float a0 = b2, a1 = 0.f, a2 = 0.f, a3 = 0.f;
            const float* hold = ph + sbb * 2048 + ((t & (SKIPN - 1)) << 7);
            const float* w = k2s + ssl * L4_WSTRIDE;
#pragma unroll 8
            for (int k = 0; k < 128; k += 4) {
                float4 h4 = *(const float4*)(hold + k);
                float4 w4 = *(const float4*)(w + k);
                a0 = fmaf(h4.x, w4.x, a0);
                a1 = fmaf(h4.y, w4.y, a1);
                a2 = fmaf(h4.z, w4.z, a2);
                a3 = fmaf(h4.w, w4.w, a3);
            }
            float acc = (a0 + a1) + (a2 + a3);
            const int si = sbb * 1280 + par + 512 + gs;
            spre[si] = acc;
            st_cluster_f32(rspre + si * 4, acc);
        }
        CLUSTER_SYNC();
        if (tid < 256) {
            const int j = tid >> 1, eb = tid & 1;
            const float* sp = spre + eb * 1280 + par;
            float gi = sigm(sp[j]);
            float gf = sigm(sp[128 + j]);
            float cb = tanhf(sp[256 + j]);
            float go = sigm(sp[384 + j]);
            float c  = gf * sc[eb * 128 + j] + gi * cb;
            float hs = sigm(sp[512 + j]);
            float h  = s0e * (go * tanhf(c)) + (1.0f - s0e) * hs;
            float* sgb = sg + eb * 512;
            sgb[j] = gi; sgb[128 + j] = gf; sgb[256 + j] = c; sgb[384 + j] = go;
            sc[eb * 128 + j] = c;
            ph[eb * 2048 + ((t & (SKIPN - 1)) << 7) + j] = h;
            sh[eb * 128 + j] = h;
        }
        __syncthreads();
    }

    // ---------------- decoder setup ----------------
    // xpd[bb][gcol] = dec_b[gcol] + sum_k sh[bb][k] * dec_k[k][gcol]
    if (tid < 512) {
        float a0 = dec_b[gcol], a1 = 0.f, a2 = 0.f, a3 = 0.f;
        const float* shb = sh + bb * 128;
#pragma unroll 4
        for (int k = 0; k < 128; k += 4) {
            a0 = fmaf(shb[k + 0], dec_k[(k + 0) * 512 + gcol], a0);
            a1 = fmaf(shb[k + 1], dec_k[(k + 1) * 512 + gcol], a1);
            a2 = fmaf(shb[k + 2], dec_k[(k + 2) * 512 + gcol], a2);
            a3 = fmaf(shb[k + 3], dec_k[(k + 3) * 512 + gcol], a3);
        }
        xpd[bb * 512 + gcol] = (a0 + a1) + (a2 + a3);
    }
    __syncthreads();   // sh fully consumed before state re-zero
    l4_fill(tid, rank, ws, k2s, dec_rk, dec_k2);
    for (int i = tid; i < 1024; i += 640) sg[i] = 0.f;
    for (int i = tid; i < 256;  i += 640) sc[i] = 0.f;
    for (int i = tid; i < 4096; i += 640) ph[i] = 0.f;
    if (tid >= 512) b2 = dec_b2[gs];
    __syncthreads();

    // ---------------- decoder loop ----------------
    for (int t = 0; t < TSTEPS; t++) {
        const int par = (t & 1) * 640;
        if (tid < 512) {
            float a0 = xpd[bb * 512 + gcol];
            float a1 = 0.f, a2 = 0.f, a3 = 0.f;
            const float* sv = sg + bb * 512 + (q << 7);
            const float* w  = ws + col * L4_WSTRIDE;
#pragma unroll 8
            for (int k = 0; k < 128; k += 4) {
                float4 s4 = *(const float4*)(sv + k);
                float4 w4 = *(const float4*)(w + k);
                a0 = fmaf(s4.x, w4.x, a0);
                a1 = fmaf(s4.y, w4.y, a1);
                a2 = fmaf(s4.z, w4.z, a2);
                a3 = fmaf(s4.w, w4.w, a3);
            }
            float acc = (a0 + a1) + (a2 + a3);
            const int si = bb * 1280 + par + gcol;
            spre[si] = acc;
            st_cluster_f32(rspre + si * 4, acc);
        } else {
            float a0 = b2, a1 = 0.f, a2 = 0.f, a3 = 0.f;
            const float* hold = ph + sbb * 2048 + ((t & (SKIPN - 1)) << 7);
            const float* w = k2s + ssl * L4_WSTRIDE;
#pragma unroll 8
            for (int k = 0; k < 128; k += 4) {
                float4 h4 = *(const float4*)(hold + k);
                float4 w4 = *(const float4*)(w + k);
                a0 = fmaf(h4.x, w4.x, a0);
                a1 = fmaf(h4.y, w4.y, a1);
                a2 = fmaf(h4.z, w4.z, a2);
                a3 = fmaf(h4.w, w4.w, a3);
            }
            float acc = (a0 + a1) + (a2 + a3);
            const int si = sbb * 1280 + par + 512 + gs;
            spre[si] = acc;
            st_cluster_f32(rspre + si * 4, acc);
        }
        CLUSTER_SYNC();
        if (tid < 256) {
            const int j = tid >> 1, eb = tid & 1;
            const float* sp = spre + eb * 1280 + par;
            float gi = sigm(sp[j]);
            float gf = sigm(sp[128 + j]);
            float cb = tanhf(sp[256 + j]);
            float go = sigm(sp[384 + j]);
            float c  = gf * sc[eb * 128 + j] + gi * cb;
            float hs = sigm(sp[512 + j]);
            float h  = s0d * (go * tanhf(c)) + (1.0f - s0d) * hs;
            float* sgb = sg + eb * 512;
            sgb[j] = gi; sgb[128 + j] = gf; sgb[256 + j] = c; sgb[384 + j] = go;
            sc[eb * 128 + j] = c;
            ph[eb * 2048 + ((t & (SKIPN - 1)) << 7) + j] = h;
            sh[eb * 128 + j] = h;
            if (rank == 0) g_flat[(size_t)(b0 + eb) * FLATN + t * 128 + j] = h;
        }
        __syncthreads();
    }
}

// ================= Kernel 3: dense layer via mma.sync tf32 =================
#define DK_ROWSTRIDE 36
#define DK_ASTG      (128 * DK_ROWSTRIDE)
#define DK_BSTG      (64 * DK_ROWSTRIDE)
#define DK_STGF      (DK_ASTG + DK_BSTG)
#define DK_STAGES    4
#define DK_SMEM      (DK_STAGES * DK_STGF * 4)

__device__ __forceinline__ void dk_load(uint32_t sb, int buf, int chunk,
                                        const float* __restrict__ W, int j0, int tid) {
    const int k0 = chunk * 32;
    const uint32_t stg = sb + (uint32_t)buf * (DK_STGF * 4);
    {
        const int r = tid >> 1;
        const int h = (tid & 1) * 16;
        const float* g = W + (size_t)(j0 + r) * FLATN + k0 + h;
        uint32_t d = stg + (uint32_t)r * (DK_ROWSTRIDE * 4) + h * 4;
#pragma unroll
        for (int i = 0; i < 4; i++) cp16(d + i * 16, g + i * 4);
    }
    {
        const int r = tid & 63;
        const int h = (tid >> 6) * 8;
        const float* g = g_flat + (size_t)r * FLATN + k0 + h;
        uint32_t d = stg + (uint32_t)(DK_ASTG * 4) + (uint32_t)r * (DK_ROWSTRIDE * 4) + h * 4;
#pragma unroll
        for (int i = 0; i < 2; i++) cp16(d + i * 16, g + i * 4);
    }
}

__global__ __launch_bounds__(256, 1) void k_dense_mma(const float* __restrict__ W,
                                                      const float* __restrict__ db,
                                                      float* __restrict__ out) {
    extern __shared__ __align__(16) float smem[];
    const uint32_t sb = smem_u32(smem);
    const int tid = threadIdx.x;
    const int wid = tid >> 5, lid = tid & 31;
    const int g = lid >> 2, tig = lid & 3;
    const int warp_m = wid & 3, warp_n = wid >> 2;
    const int j0 = blockIdx.x * 128;

    float acc[2][4][4];
#pragma unroll
    for (int mt = 0; mt < 2; mt++)
#pragma unroll
        for (int nt = 0; nt < 4; nt++)
#pragma unroll
            for (int r = 0; r < 4; r++) acc[mt][nt][r] = 0.f;

#pragma unroll
    for (int s = 0; s < 3; s++) {
        dk_load(sb, s, s, W, j0, tid);
        asm volatile("cp.async.commit_group;" ::: "memory");
    }

    const int jwA = warp_m * 32 + g;
    const int bwB = warp_n * 32 + g;

    for (int c = 0; c < 512; c++) {
        asm volatile("cp.async.wait_group 2;" ::: "memory");
        __syncthreads();

        if (c + 3 < 512) dk_load(sb, (c + 3) & 3, c + 3, W, j0, tid);
        asm volatile("cp.async.commit_group;" ::: "memory");

        const float* As = smem + (c & 3) * DK_STGF;
        const float* Bs = As + DK_ASTG;
#pragma unroll
        for (int ks = 0; ks < 4; ks++) {
            const int kk = ks * 8 + tig;
            uint32_t a[2][4];
#pragma unroll
            for (int mt = 0; mt < 2; mt++) {
                const float* ar = As + (jwA + mt * 16) * DK_ROWSTRIDE + kk;
                a[mt][0] = f2tf32(ar[0]);
                a[mt][1] = f2tf32(ar[8 * DK_ROWSTRIDE]);
                a[mt][2] = f2tf32(ar[4]);
                a[mt][3] = f2tf32(ar[8 * DK_ROWSTRIDE + 4]);
            }
#pragma unroll
            for (int nt = 0; nt < 4; nt++) {
                const float* br = Bs + (bwB + nt * 8) * DK_ROWSTRIDE + kk;
                uint32_t b0 = f2tf32(br[0]);
                uint32_t b1 = f2tf32(br[4]);
                mma16n8k8(acc[0][nt], a[0], b0, b1);
                mma16n8k8(acc[1][nt], a[1], b0, b1);
            }
        }
    }

#pragma unroll
    for (int mt = 0; mt < 2; mt++) {
        const int jr0 = j0 + warp_m * 32 + mt * 16 + g;
        const float bj0 = db[jr0];
        const float bj8 = db[jr0 + 8];
#pragma unroll
        for (int nt = 0; nt < 4; nt++) {
            const int bb = warp_n * 32 + nt * 8 + 2 * tig;
            out[(size_t)bb * FLATN + jr0]           = acc[mt][nt][0] + bj0;
            out[(size_t)(bb + 1) * FLATN + jr0]     = acc[mt][nt][1] + bj0;
            out[(size_t)bb * FLATN + jr0 + 8]       = acc[mt][nt][2] + bj8;
            out[(size_t)(bb + 1) * FLATN + jr0 + 8] = acc[mt][nt][3] + bj8;
        }
    }
}

// ================= launch =================
extern "C" void kernel_launch(void* const* d_in, const int* in_sizes, int n_in,
                              void* d_out, int out_size) {
    const float* X      = (const float*)d_in[0];
    const float* enc_k  = (const float*)d_in[1];
    const float* enc_rk = (const float*)d_in[2];
    const float* enc_k2 = (const float*)d_in[3];
    const float* enc_b  = (const float*)d_in[4];
    const float* enc_b2 = (const float*)d_in[5];
    const float* enc_s0 = (const float*)d_in[6];
    const float* dec_k  = (const float*)d_in[7];
    const float* dec_rk = (const float*)d_in[8];
    const float* dec_k2 = (const float*)d_in[9];
    const float* dec_b  = (const float*)d_in[10];
    const float* dec_b2 = (const float*)d_in[11];
    const float* dec_s0 = (const float*)d_in[12];
    const float* dw     = (const float*)d_in[13];
    const float* db     = (const float*)d_in[14];
    float* out = (float*)d_out;

    cudaFuncSetAttribute(k_lstm4, cudaFuncAttributeMaxDynamicSharedMemorySize, L4_SMEM);
    cudaFuncSetAttribute(k_dense_mma, cudaFuncAttributeMaxDynamicSharedMemorySize, DK_SMEM);

    k_xproj<<<512, 128>>>(X, enc_k, enc_b);
    k_lstm4<<<64, 640, L4_SMEM>>>(enc_rk, enc_k2, enc_b2, enc_s0,
                                  dec_k, dec_rk, dec_k2, dec_b, dec_b2, dec_s0);
    k_dense_mma<<<128, 256, DK_SMEM>>>(dw, db, out);
}

// round 14
// speedup vs baseline: 1.3355x; 1.3355x over previous
#include <cuda_runtime.h>
#include <cstdint>

#define U        128
#define G4       512
#define SKIPN    16
#define TSTEPS   128
#define BATCH    64
#define FLATN    16384   // SEQ * UNITS

// Scratch (device globals: allocation-free rule)
__device__ float g_xpe[8192 * 512];      // encoder input projections, row = t*64+b
__device__ float g_flat[BATCH * FLATN];  // decoder outputs (dense GEMM B-matrix)

__device__ __forceinline__ float sigm(float x) { return 1.0f / (1.0f + expf(-x)); }

__device__ __forceinline__ uint32_t smem_u32(const void* p) {
    uint32_t a;
    asm("{ .reg .u64 t; cvta.to.shared.u64 t, %1; cvt.u32.u64 %0, t; }" : "=r"(a) : "l"(p));
    return a;
}
__device__ __forceinline__ void cp16(uint32_t dst, const float* src) {
    asm volatile("cp.async.cg.shared.global [%0], [%1], 16;" :: "r"(dst), "l"(src));
}
__device__ __forceinline__ uint32_t f2tf32(float f) {
    uint32_t r;
    asm("cvt.rna.tf32.f32 %0, %1;" : "=r"(r) : "f"(f));
    return r;
}
__device__ __forceinline__ void mma16n8k8(float* c, const uint32_t* a, uint32_t b0, uint32_t b1) {
    asm volatile(
        "mma.sync.aligned.m16n8k8.row.col.f32.tf32.tf32.f32 "
        "{%0,%1,%2,%3}, {%4,%5,%6,%7}, {%8,%9}, {%0,%1,%2,%3};"
        : "+f"(c[0]), "+f"(c[1]), "+f"(c[2]), "+f"(c[3])
        : "r"(a[0]), "r"(a[1]), "r"(a[2]), "r"(a[3]), "r"(b0), "r"(b1));
}
__device__ __forceinline__ uint32_t ctarank() {
    uint32_t r; asm("mov.u32 %0, %%cluster_ctarank;" : "=r"(r)); return r;
}
__device__ __forceinline__ uint32_t mapa_u32(uint32_t a, uint32_t rank) {
    uint32_t o; asm("mapa.shared::cluster.u32 %0, %1, %2;" : "=r"(o) : "r"(a), "r"(rank)); return o;
}
__device__ __forceinline__ void st_cluster_f32(uint32_t addr, float v) {
    asm volatile("st.shared::cluster.f32 [%0], %1;" :: "r"(addr), "f"(v) : "memory");
}
#define CLUSTER_SYNC() do { \
    asm volatile("barrier.cluster.arrive.aligned;" ::: "memory"); \
    asm volatile("barrier.cluster.wait.aligned;" ::: "memory"); \
} while (0)

// ================= Kernel 1: encoder input projection =================
__global__ __launch_bounds__(128) void k_xproj(const float* __restrict__ X,
                                               const float* __restrict__ Wk,
                                               const float* __restrict__ bias) {
    __shared__ float As[128 * 16];   // [k][r] transposed
    const int tid  = threadIdx.x;
    const int row0 = blockIdx.x * 16;

    for (int idx = tid; idx < 16 * 128; idx += 128) {
        int r = idx >> 7, m = idx & 127;
        int row = row0 + r;
        int t = row >> 6, b = row & 63;
        As[m * 16 + r] = X[(size_t)b * 32768 + t * 128 + m];
    }
    __syncthreads();

    const int c0 = tid * 4;
    float4 bs = *(const float4*)(bias + c0);
    float acc[16][4];
#pragma unroll
    for (int r = 0; r < 16; r++) { acc[r][0] = bs.x; acc[r][1] = bs.y; acc[r][2] = bs.z; acc[r][3] = bs.w; }

#pragma unroll 4
    for (int k = 0; k < 128; k++) {
        float4 w = *(const float4*)(Wk + k * 512 + c0);
#pragma unroll
        for (int r = 0; r < 16; r++) {
            float a = As[k * 16 + r];
            acc[r][0] = fmaf(a, w.x, acc[r][0]);
            acc[r][1] = fmaf(a, w.y, acc[r][1]);
            acc[r][2] = fmaf(a, w.z, acc[r][2]);
            acc[r][3] = fmaf(a, w.w, acc[r][3]);
        }
    }
#pragma unroll
    for (int r = 0; r < 16; r++) {
        float4 o; o.x = acc[r][0]; o.y = acc[r][1]; o.z = acc[r][2]; o.w = acc[r][3];
        *(float4*)(g_xpe + (size_t)(row0 + r) * 512 + c0) = o;
    }
}

// ====== Kernel 2: clustered skip-LSTM, REGISTER-resident weights ============
// Cluster of 2 CTAs per batch; rank r owns gate cols [r*256,r*256+256) and
// skip cols [r*64,r*64+64). 640 threads: tid<512 gate (2 threads/col, one
// 64-k half each, 64 weight regs), tid>=512 skip (2 threads/col likewise).
// Pair partials combined with shfl.bfly(1); even lane publishes spre locally
// and to the peer CTA (DSMEM), one cluster.sync/step, elementwise replicated.
__global__ __launch_bounds__(640, 1) __cluster_dims__(2, 1, 1)
void k_lstm5(
    const float* __restrict__ enc_rk, const float* __restrict__ enc_k2,
    const float* __restrict__ enc_b2, const float* __restrict__ enc_s0p,
    const float* __restrict__ dec_k,  const float* __restrict__ dec_rk,
    const float* __restrict__ dec_k2, const float* __restrict__ dec_b,
    const float* __restrict__ dec_b2, const float* __restrict__ dec_s0p) {
    __shared__ __align__(16) float sg[512];
    __shared__ __align__(16) float sc[128];
    __shared__ __align__(16) float sh[128];
    __shared__ __align__(16) float ph[SKIPN * 128];
    __shared__ __align__(16) float spre[1280];   // 2 parity buffers x 640

    const int tid  = threadIdx.x;
    const int rank = (int)ctarank();
    const int b    = blockIdx.x >> 1;
    const uint32_t spre_l = smem_u32(spre);
    const uint32_t spre_r = mapa_u32(spre_l, 1 - rank);

    const bool isGate = tid < 512;
    // gate role
    const int col   = tid >> 1;                 // 0..255
    const int half  = tid & 1;                  // k-half
    const int gcol  = rank * 256 + col;         // global gate column
    const int q     = gcol >> 7;                // quadrant (warp-uniform)
    // skip role
    const int sid   = tid - 512;
    const int scl   = sid >> 1;                 // 0..63
    const int gs    = rank * 64 + scl;          // global skip column
    const int kbase = half * 64;                // same bit for skip (tid&1)

    // -------- encoder: load weights into registers --------
    float wreg[64];
    if (isGate) {
#pragma unroll
        for (int i = 0; i < 64; i++) wreg[i] = enc_rk[(kbase + i) * 512 + gcol];
    } else {
#pragma unroll
        for (int i = 0; i < 64; i++) wreg[i] = enc_k2[(kbase + i) * 128 + gs];
    }
    float b2 = (!isGate && half == 0) ? enc_b2[gs] : 0.f;

    for (int i = tid; i < 512; i += 640) sg[i] = 0.f;
    for (int i = tid; i < 128; i += 640) sc[i] = 0.f;
    for (int i = tid; i < SKIPN * 128; i += 640) ph[i] = 0.f;
    const float s0e = *enc_s0p;
    const float s0d = *dec_s0p;
    __syncthreads();

    // -------- encoder loop --------
    for (int t = 0; t < TSTEPS; t++) {
        const int par = (t & 1) * 640;
        float a0, a1 = 0.f, a2 = 0.f, a3 = 0.f;
        const float* sv;
        if (isGate) {
            a0 = (half == 0) ? g_xpe[((size_t)t * 64 + b) * 512 + gcol] : 0.f;
            sv = sg + (q << 7) + kbase;
        } else {
            a0 = b2;
            sv = ph + ((t & (SKIPN - 1)) << 7) + kbase;
        }
#pragma unroll
        for (int i = 0; i < 16; i++) {
            float4 s4 = *(const float4*)(sv + 4 * i);
            a0 = fmaf(s4.x, wreg[4 * i + 0], a0);
            a1 = fmaf(s4.y, wreg[4 * i + 1], a1);
            a2 = fmaf(s4.z, wreg[4 * i + 2], a2);
            a3 = fmaf(s4.w, wreg[4 * i + 3], a3);
        }
        float acc = (a0 + a1) + (a2 + a3);
        acc += __shfl_xor_sync(0xFFFFFFFFu, acc, 1);
        if (half == 0) {
            const int si = par + (isGate ? gcol : 512 + gs);
            spre[si] = acc;
            st_cluster_f32(spre_r + si * 4, acc);
        }
        CLUSTER_SYNC();
        if (tid < 128) {
            const int j = tid;
            const float* sp = spre + par;
            float gi = sigm(sp[j]);
            float gf = sigm(sp[128 + j]);
            float cb = tanhf(sp[256 + j]);
            float go = sigm(sp[384 + j]);
            float c  = gf * sc[j] + gi * cb;
            float hs = sigm(sp[512 + j]);
            float h  = s0e * (go * tanhf(c)) + (1.0f - s0e) * hs;
            sg[j] = gi; sg[128 + j] = gf; sg[256 + j] = c; sg[384 + j] = go;
            sc[j] = c;
            ph[((t & (SKIPN - 1)) << 7) + j] = h;
            sh[j] = h;
        }
        __syncthreads();
    }

    // -------- decoder setup --------
    // per-column constant input projection kept in a register
    float r_xpd = 0.f;
    if (isGate && half == 0) {
        float x0 = dec_b[gcol], x1 = 0.f, x2 = 0.f, x3 = 0.f;
#pragma unroll 4
        for (int k = 0; k < 128; k += 4) {
            x0 = fmaf(sh[k + 0], dec_k[(k + 0) * 512 + gcol], x0);
            x1 = fmaf(sh[k + 1], dec_k[(k + 1) * 512 + gcol], x1);
            x2 = fmaf(sh[k + 2], dec_k[(k + 2) * 512 + gcol], x2);
            x3 = fmaf(sh[k + 3], dec_k[(k + 3) * 512 + gcol], x3);
        }
        r_xpd = (x0 + x1) + (x2 + x3);
    }
    // reload weights (decoder)
    if (isGate) {
#pragma unroll
        for (int i = 0; i < 64; i++) wreg[i] = dec_rk[(kbase + i) * 512 + gcol];
    } else {
#pragma unroll
        for (int i = 0; i < 64; i++) wreg[i] = dec_k2[(kbase + i) * 128 + gs];
        if (half == 0) b2 = dec_b2[gs];
    }
    __syncthreads();   // sh fully consumed before state re-zero
    for (int i = tid; i < 512; i += 640) sg[i] = 0.f;
    for (int i = tid; i < 128; i += 640) sc[i] = 0.f;
    for (int i = tid; i < SKIPN * 128; i += 640) ph[i] = 0.f;
    __syncthreads();

    // -------- decoder loop --------
    for (int t = 0; t < TSTEPS; t++) {
        const int par = (t & 1) * 640;
        float a0, a1 = 0.f, a2 = 0.f, a3 = 0.f;
        const float* sv;
        if (isGate) {
            a0 = r_xpd;              // zero for half==1
            sv = sg + (q << 7) + kbase;
        } else {
            a0 = b2;
            sv = ph + ((t & (SKIPN - 1)) << 7) + kbase;
        }
#pragma unroll
        for (int i = 0; i < 16; i++) {
            float4 s4 = *(const float4*)(sv + 4 * i);
            a0 = fmaf(s4.x, wreg[4 * i + 0], a0);
            a1 = fmaf(s4.y, wreg[4 * i + 1], a1);
            a2 = fmaf(s4.z, wreg[4 * i + 2], a2);
            a3 = fmaf(s4.w, wreg[4 * i + 3], a3);
        }
        float acc = (a0 + a1) + (a2 + a3);
        acc += __shfl_xor_sync(0xFFFFFFFFu, acc, 1);
        if (half == 0) {
            const int si = par + (isGate ? gcol : 512 + gs);
            spre[si] = acc;
            st_cluster_f32(spre_r + si * 4, acc);
        }
        CLUSTER_SYNC();
        if (tid < 128) {
            const int j = tid;
            const float* sp = spre + par;
            float gi = sigm(sp[j]);
            float gf = sigm(sp[128 + j]);
            float cb = tanhf(sp[256 + j]);
            float go = sigm(sp[384 + j]);
            float c  = gf * sc[j] + gi * cb;
            float hs = sigm(sp[512 + j]);
            float h  = s0d * (go * tanhf(c)) + (1.0f - s0d) * hs;
            sg[j] = gi; sg[128 + j] = gf; sg[256 + j] = c; sg[384 + j] = go;
            sc[j] = c;
            ph[((t & (SKIPN - 1)) << 7) + j] = h;
            sh[j] = h;
            if (rank == 0) g_flat[(size_t)b * FLATN + t * 128 + j] = h;
        }
        __syncthreads();
    }
}

// ================= Kernel 3: dense layer via mma.sync tf32 =================
#define DK_ROWSTRIDE 36
#define DK_ASTG      (128 * DK_ROWSTRIDE)
#define DK_BSTG      (64 * DK_ROWSTRIDE)
#define DK_STGF      (DK_ASTG + DK_BSTG)
#define DK_STAGES    4
#define DK_SMEM      (DK_STAGES * DK_STGF * 4)

__device__ __forceinline__ void dk_load(uint32_t sb, int buf, int chunk,
                                        const float* __restrict__ W, int j0, int tid) {
    const int k0 = chunk * 32;
    const uint32_t stg = sb + (uint32_t)buf * (DK_STGF * 4);
    {
        const int r = tid >> 1;
        const int h = (tid & 1) * 16;
        const float* g = W + (size_t)(j0 + r) * FLATN + k0 + h;
        uint32_t d = stg + (uint32_t)r * (DK_ROWSTRIDE * 4) + h * 4;
#pragma unroll
        for (int i = 0; i < 4; i++) cp16(d + i * 16, g + i * 4);
    }
    {
        const int r = tid & 63;
        const int h = (tid >> 6) * 8;
        const float* g = g_flat + (size_t)r * FLATN + k0 + h;
        uint32_t d = stg + (uint32_t)(DK_ASTG * 4) + (uint32_t)r * (DK_ROWSTRIDE * 4) + h * 4;
#pragma unroll
        for (int i = 0; i < 2; i++) cp16(d + i * 16, g + i * 4);
    }
}

__global__ __launch_bounds__(256, 1) void k_dense_mma(const float* __restrict__ W,
                                                      const float* __restrict__ db,
                                                      float* __restrict__ out) {
    extern __shared__ __align__(16) float smem[];
    const uint32_t sb = smem_u32(smem);
    const int tid = threadIdx.x;
    const int wid = tid >> 5, lid = tid & 31;
    const int g = lid >> 2, tig = lid & 3;
    const int warp_m = wid & 3, warp_n = wid >> 2;
    const int j0 = blockIdx.x * 128;

    float acc[2][4][4];
#pragma unroll
    for (int mt = 0; mt < 2; mt++)
#pragma unroll
        for (int nt = 0; nt < 4; nt++)
#pragma unroll
            for (int r = 0; r < 4; r++) acc[mt][nt][r] = 0.f;

#pragma unroll
    for (int s = 0; s < 3; s++) {
        dk_load(sb, s, s, W, j0, tid);
        asm volatile("cp.async.commit_group;" ::: "memory");
    }

    const int jwA = warp_m * 32 + g;
    const int bwB = warp_n * 32 + g;

    for (int c = 0; c < 512; c++) {
        asm volatile("cp.async.wait_group 2;" ::: "memory");
        __syncthreads();

        if (c + 3 < 512) dk_load(sb, (c + 3) & 3, c + 3, W, j0, tid);
        asm volatile("cp.async.commit_group;" ::: "memory");

        const float* As = smem + (c & 3) * DK_STGF;
        const float* Bs = As + DK_ASTG;
#pragma unroll
        for (int ks = 0; ks < 4; ks++) {
            const int kk = ks * 8 + tig;
            uint32_t a[2][4];
#pragma unroll
            for (int mt = 0; mt < 2; mt++) {
                const float* ar = As + (jwA + mt * 16) * DK_ROWSTRIDE + kk;
                a[mt][0] = f2tf32(ar[0]);
                a[mt][1] = f2tf32(ar[8 * DK_ROWSTRIDE]);
                a[mt][2] = f2tf32(ar[4]);
                a[mt][3] = f2tf32(ar[8 * DK_ROWSTRIDE + 4]);
            }
#pragma unroll
            for (int nt = 0; nt < 4; nt++) {
                const float* br = Bs + (bwB + nt * 8) * DK_ROWSTRIDE + kk;
                uint32_t b0 = f2tf32(br[0]);
                uint32_t b1 = f2tf32(br[4]);
                mma16n8k8(acc[0][nt], a[0], b0, b1);
                mma16n8k8(acc[1][nt], a[1], b0, b1);
            }
        }
    }

#pragma unroll
    for (int mt = 0; mt < 2; mt++) {
        const int jr0 = j0 + warp_m * 32 + mt * 16 + g;
        const float bj0 = db[jr0];
        const float bj8 = db[jr0 + 8];
#pragma unroll
        for (int nt = 0; nt < 4; nt++) {
            const int bb = warp_n * 32 + nt * 8 + 2 * tig;
            out[(size_t)bb * FLATN + jr0]           = acc[mt][nt][0] + bj0;
            out[(size_t)(bb + 1) * FLATN + jr0]     = acc[mt][nt][1] + bj0;
            out[(size_t)bb * FLATN + jr0 + 8]       = acc[mt][nt][2] + bj8;
            out[(size_t)(bb + 1) * FLATN + jr0 + 8] = acc[mt][nt][3] + bj8;
        }
    }
}

// ================= launch =================
extern "C" void kernel_launch(void* const* d_in, const int* in_sizes, int n_in,
                              void* d_out, int out_size) {
    const float* X      = (const float*)d_in[0];
    const float* enc_k  = (const float*)d_in[1];
    const float* enc_rk = (const float*)d_in[2];
    const float* enc_k2 = (const float*)d_in[3];
    const float* enc_b  = (const float*)d_in[4];
    const float* enc_b2 = (const float*)d_in[5];
    const float* enc_s0 = (const float*)d_in[6];
    const float* dec_k  = (const float*)d_in[7];
    const float* dec_rk = (const float*)d_in[8];
    const float* dec_k2 = (const float*)d_in[9];
    const float* dec_b  = (const float*)d_in[10];
    const float* dec_b2 = (const float*)d_in[11];
    const float* dec_s0 = (const float*)d_in[12];
    const float* dw     = (const float*)d_in[13];
    const float* db     = (const float*)d_in[14];
    float* out = (float*)d_out;

    cudaFuncSetAttribute(k_dense_mma, cudaFuncAttributeMaxDynamicSharedMemorySize, DK_SMEM);

    k_xproj<<<512, 128>>>(X, enc_k, enc_b);
    k_lstm5<<<128, 640>>>(enc_rk, enc_k2, enc_b2, enc_s0,
                          dec_k, dec_rk, dec_k2, dec_b, dec_b2, dec_s0);
    k_dense_mma<<<128, 256, DK_SMEM>>>(dw, db, out);
}